// round 6
// baseline (speedup 1.0000x reference)
#include <cuda_runtime.h>
#include <cstdint>

#define BB 4
#define HH 48
#define WW 48
#define CC 128

typedef unsigned long long u64;

// ---------------- scratch (device globals; no allocation allowed) ----------
__device__ float g_Q [BB*HH*WW*CC];      // queries per pixel
__device__ float g_KV[BB*HH*WW*256];     // per-pixel KV projection (K|V)
__device__ float g_KVmid[BB*24*24*256];  // 2x2 pooled KV
__device__ float g_KVglo[BB*12*12*256];  // 4x4 pooled KV

__device__ __forceinline__ float ex2f(float x) {
    float r; asm("ex2.approx.f32 %0, %1;" : "=f"(r) : "f"(x)); return r;
}
__device__ __forceinline__ u64 ffma2(u64 a, u64 b, u64 c) {
    u64 d; asm("fma.rn.f32x2 %0,%1,%2,%3;" : "=l"(d) : "l"(a), "l"(b), "l"(c)); return d;
}
__device__ __forceinline__ u64 fmul2(u64 a, u64 b) {
    u64 d; asm("mul.rn.f32x2 %0,%1,%2;" : "=l"(d) : "l"(a), "l"(b)); return d;
}
__device__ __forceinline__ u64 fadd2(u64 a, u64 b) {
    u64 d; asm("add.rn.f32x2 %0,%1,%2;" : "=l"(d) : "l"(a), "l"(b)); return d;
}
__device__ __forceinline__ u64 pk2(float lo, float hi) {
    u64 d; asm("mov.b64 %0,{%1,%2};" : "=l"(d) : "f"(lo), "f"(hi)); return d;
}
__device__ __forceinline__ void up2(u64 v, float& lo, float& hi) {
    asm("mov.b64 {%0,%1},%2;" : "=f"(lo), "=f"(hi) : "l"(v));
}
__device__ __forceinline__ void cp16(uint32_t dst, const float* src) {
    asm volatile("cp.async.cg.shared.global [%0], [%1], 16;" :: "r"(dst), "l"(src));
}

// ============================================================================
// Kernel 01: fused NCHW->pixel load (+ LayerNorm for Q path) + projection GEMM.
//   grid (144, 3): sub 0: Q = LN(F) @ q_w^T + q_b
//                  sub 1: K = F @ kv_w[0:128]^T + kv_b[:128]
//                  sub 2: V = F @ kv_w[128:]^T  + kv_b[128:]
//   Each CTA owns 64 consecutive pixels (same batch).  A tile lives in smem.
// ============================================================================
__global__ void __launch_bounds__(256)
k01_proj(const float* __restrict__ feat,
         const float* __restrict__ lnw, const float* __restrict__ lnb,
         const float* __restrict__ qw,  const float* __restrict__ qb,
         const float* __restrict__ kvw, const float* __restrict__ kvb) {
    __shared__ float sA[64][132];
    __shared__ float sB[128][20];

    int sub   = blockIdx.y;
    int mBase = blockIdx.x * 64;
    int b     = mBase / 2304;
    int rem0  = mBase % 2304;
    int tid   = threadIdx.x;

    // load 64 pixels x 128 channels from NCHW (coalesced along pixels)
    const float* fb = feat + (size_t)b * CC * 2304 + rem0;
#pragma unroll
    for (int i = 0; i < 32; i++) {
        int f = tid + i*256;
        int c = f >> 6, p = f & 63;
        sA[p][c] = fb[(size_t)c * 2304 + p];
    }
    __syncthreads();

    if (sub == 0) {
        // in-place LayerNorm: 4 threads per pixel
        int p = tid >> 2, tg = tid & 3;
        float s = 0.f, ss = 0.f;
#pragma unroll
        for (int k = 0; k < 32; k++) {
            float v = sA[p][tg*32 + k];
            s += v; ss += v*v;
        }
        s  += __shfl_xor_sync(0xffffffffu, s, 1);
        ss += __shfl_xor_sync(0xffffffffu, ss, 1);
        s  += __shfl_xor_sync(0xffffffffu, s, 2);
        ss += __shfl_xor_sync(0xffffffffu, ss, 2);
        float mean = s * (1.f/128.f);
        float var  = ss * (1.f/128.f) - mean*mean;
        float rstd = rsqrtf(var + 1e-5f);
#pragma unroll
        for (int k = 0; k < 32; k++) {
            int c = tg*32 + k;
            sA[p][c] = (sA[p][c] - mean) * rstd * lnw[c] + lnb[c];
        }
        __syncthreads();
    }

    const float* Wm   = (sub == 0) ? qw : (kvw + (size_t)(sub-1)*128*128);
    const float* bias = (sub == 0) ? qb : (kvb + (sub-1)*128);

    int mg = tid & 15;
    int ng = tid >> 4;

    float acc[4][8];
#pragma unroll
    for (int m = 0; m < 4; m++)
#pragma unroll
        for (int n = 0; n < 8; n++) acc[m][n] = 0.f;

    for (int ck = 0; ck < 8; ck++) {
        __syncthreads();
        // load B chunk: 128 x 16
#pragma unroll
        for (int i = 0; i < 2; i++) {
            int f = tid + i*256;
            int row = f >> 2, kq = f & 3;
            *(float4*)&sB[row][kq*4] = *(const float4*)(Wm + (size_t)row*128 + ck*16 + kq*4);
        }
        __syncthreads();
#pragma unroll
        for (int k4 = 0; k4 < 4; k4++) {
            float4 a0 = *(const float4*)&sA[mg*4+0][ck*16 + k4*4];
            float4 a1 = *(const float4*)&sA[mg*4+1][ck*16 + k4*4];
            float4 a2 = *(const float4*)&sA[mg*4+2][ck*16 + k4*4];
            float4 a3 = *(const float4*)&sA[mg*4+3][ck*16 + k4*4];
#pragma unroll
            for (int n = 0; n < 8; n++) {
                float4 bv = *(const float4*)&sB[ng*8+n][k4*4];
                acc[0][n] += a0.x*bv.x + a0.y*bv.y + a0.z*bv.z + a0.w*bv.w;
                acc[1][n] += a1.x*bv.x + a1.y*bv.y + a1.z*bv.z + a1.w*bv.w;
                acc[2][n] += a2.x*bv.x + a2.y*bv.y + a2.z*bv.z + a2.w*bv.w;
                acc[3][n] += a3.x*bv.x + a3.y*bv.y + a3.z*bv.z + a3.w*bv.w;
            }
        }
    }

    float4 bv0 = *(const float4*)(bias + ng*8);
    float4 bv1 = *(const float4*)(bias + ng*8 + 4);
    int stride = (sub == 0) ? 128 : 256;
    float* base = (sub == 0) ? (g_Q + ng*8) : (g_KV + (sub-1)*128 + ng*8);
#pragma unroll
    for (int m = 0; m < 4; m++) {
        float* dst = base + (size_t)(mBase + mg*4 + m) * stride;
        float4 r0 = make_float4(acc[m][0]+bv0.x, acc[m][1]+bv0.y, acc[m][2]+bv0.z, acc[m][3]+bv0.w);
        float4 r1 = make_float4(acc[m][4]+bv1.x, acc[m][5]+bv1.y, acc[m][6]+bv1.z, acc[m][7]+bv1.w);
        *(float4*)dst       = r0;
        *((float4*)dst + 1) = r1;
    }
}

// ============================================================================
// Kernel 2: pooled KV.  Unchanged.
// ============================================================================
__global__ void k2_pool() {
    int t = blockIdx.x;
    int c = threadIdx.x;
    if (t < BB*576) {
        int b = t / 576, r = t % 576, my = r / 24, mx = r % 24;
        const float* base = g_KV + ((size_t)((b*48 + my*2)*48 + mx*2))*256 + c;
        float v = base[0] + base[256] + base[48*256] + base[48*256 + 256];
        g_KVmid[(size_t)t*256 + c] = v * 0.25f;
    } else {
        int t2 = t - BB*576;
        int b = t2 / 144, r = t2 % 144, gy = r / 12, gx = r % 12;
        float v = 0.f;
#pragma unroll
        for (int i = 0; i < 4; i++)
#pragma unroll
            for (int j = 0; j < 4; j++)
                v += g_KV[((size_t)((b*48 + gy*4 + i)*48 + gx*4 + j))*256 + c];
        g_KVglo[(size_t)t2*256 + c] = v * (1.f/16.f);
    }
}

// ============================================================================
// Kernel 3 v5: 2x2 window group; zero-waste local phase (per-window smem
//   select); 64-token mid/glo chunks with row-split across the two warp
//   halves (all 16 warps always active); 128KB dynamic smem ring.
// ============================================================================
#define NTOK 720          // mid (576) + glo (144)
#define NCH  12           // chunks of 64 tokens (last = 16)

__global__ void __launch_bounds__(512, 1)
k3_attn(const float* __restrict__ feat, const float* __restrict__ kvb,
        const float* __restrict__ ow,   const float* __restrict__ ob,
        float* __restrict__ out) {
    extern __shared__ float ds[];     // 131072 B: ring[2][64][256]

    int cta = blockIdx.x;
    int b = cta / 36, g = cta % 36;
    int gy = g / 6, gx = g % 6;
    int tid  = threadIdx.x;
    int lane = tid & 31;
    int warp = tid >> 5;
    int h = warp & 7, th = warp >> 3;

    int qg0 = lane, qg1 = lane + 32;
    int wgA = qg0 >> 4, wgB = qg1 >> 4;     // wgA in {0,1}, wgB in {2,3}

    const float SC = 0.25f * 1.4426950408889634f;
    u64 SC2 = pk2(SC, SC);

    // ---- load 2 queries (16 dims each), pre-scaled ----
    u64 q0[8], q1[8];
    {
        int qi = qg0 & 15;
        int wy = gy*2 + (wgA>>1), wx = gx*2 + (wgA&1);
        int py = wy*4 + (qi>>2), px = wx*4 + (qi&3);
        const longlong2* qp = (const longlong2*)(g_Q + ((size_t)((b*48+py)*48+px))*128 + h*16);
#pragma unroll
        for (int i = 0; i < 4; i++) {
            longlong2 t2 = qp[i];
            q0[2*i]   = fmul2((u64)t2.x, SC2);
            q0[2*i+1] = fmul2((u64)t2.y, SC2);
        }
    }
    {
        int qi = qg1 & 15;
        int wy = gy*2 + (wgB>>1), wx = gx*2 + (wgB&1);
        int py = wy*4 + (qi>>2), px = wx*4 + (qi&3);
        const longlong2* qp = (const longlong2*)(g_Q + ((size_t)((b*48+py)*48+px))*128 + h*16);
#pragma unroll
        for (int i = 0; i < 4; i++) {
            longlong2 t2 = qp[i];
            q1[2*i]   = fmul2((u64)t2.x, SC2);
            q1[2*i+1] = fmul2((u64)t2.y, SC2);
        }
    }

    u64 acc0[8], acc1[8];
#pragma unroll
    for (int i = 0; i < 8; i++) { acc0[i] = 0ull; acc1[i] = 0ull; }
    float ls0 = 0.f, ls1 = 0.f;

    // staging map: 64 rows, 8 threads/row, 32 floats (8x cp16) each
    int srow = tid >> 3;
    int scol = (tid & 7) * 32;

    // ------------------- LOCAL PHASE: 4 sub-tiles of all 4 windows ---------
    for (int st = 0; st < 4; st++) {
        {
            int w2 = srow >> 4, j = srow & 15;
            int idx = st*16 + j;
            int y = (gy*2 + (w2>>1))*4 + (idx>>3) - 2;
            int x = (gx*2 + (w2&1))*4  + (idx&7)  - 2;
            const float* src = ((unsigned)y < 48u && (unsigned)x < 48u)
                ? (g_KV + ((size_t)((b*48+y)*48+x))*256) : kvb;
            uint32_t dst = (uint32_t)__cvta_generic_to_shared(ds + srow*256 + scol);
#pragma unroll
            for (int i = 0; i < 8; i++) cp16(dst + i*16, src + scol + i*4);
            asm volatile("cp.async.commit_group;");
            asm volatile("cp.async.wait_group 0;");
        }
        __syncthreads();

        const float* kA = ds + (wgA*16)*256 + h*16;
        const float* kB = ds + (wgB*16)*256 + h*16;
#pragma unroll 4
        for (int j = 0; j < 16; j++) {
            const longlong2* kp0 = (const longlong2*)(kA + j*256);
            longlong2 a0 = kp0[0], a1 = kp0[1], a2 = kp0[2], a3 = kp0[3];
            const longlong2* kp1 = (const longlong2*)(kB + j*256);
            longlong2 c0 = kp1[0], c1 = kp1[1], c2 = kp1[2], c3 = kp1[3];

            u64 da = ffma2(q0[1], (u64)a0.y, fmul2(q0[0], (u64)a0.x));
            da = ffma2(q0[2], (u64)a1.x, da);
            da = ffma2(q0[3], (u64)a1.y, da);
            u64 db = ffma2(q0[5], (u64)a2.y, fmul2(q0[4], (u64)a2.x));
            db = ffma2(q0[6], (u64)a3.x, db);
            db = ffma2(q0[7], (u64)a3.y, db);
            u64 d0 = fadd2(da, db);

            u64 ea = ffma2(q1[1], (u64)c0.y, fmul2(q1[0], (u64)c0.x));
            ea = ffma2(q1[2], (u64)c1.x, ea);
            ea = ffma2(q1[3], (u64)c1.y, ea);
            u64 eb = ffma2(q1[5], (u64)c2.y, fmul2(q1[4], (u64)c2.x));
            eb = ffma2(q1[6], (u64)c3.x, eb);
            eb = ffma2(q1[7], (u64)c3.y, eb);
            u64 d1 = fadd2(ea, eb);

            float a, bb;
            up2(d0, a, bb); float p0 = ex2f(a + bb);
            up2(d1, a, bb); float p1 = ex2f(a + bb);
            ls0 += p0; ls1 += p1;
            u64 P0 = pk2(p0, p0), P1 = pk2(p1, p1);

            const longlong2* vp0 = (const longlong2*)(kA + j*256 + 128);
            longlong2 v0 = vp0[0], v1 = vp0[1], v2 = vp0[2], v3 = vp0[3];
            acc0[0] = ffma2(P0, (u64)v0.x, acc0[0]);
            acc0[1] = ffma2(P0, (u64)v0.y, acc0[1]);
            acc0[2] = ffma2(P0, (u64)v1.x, acc0[2]);
            acc0[3] = ffma2(P0, (u64)v1.y, acc0[3]);
            acc0[4] = ffma2(P0, (u64)v2.x, acc0[4]);
            acc0[5] = ffma2(P0, (u64)v2.y, acc0[5]);
            acc0[6] = ffma2(P0, (u64)v3.x, acc0[6]);
            acc0[7] = ffma2(P0, (u64)v3.y, acc0[7]);
            const longlong2* vp1 = (const longlong2*)(kB + j*256 + 128);
            longlong2 w0 = vp1[0], w1 = vp1[1], w2v = vp1[2], w3 = vp1[3];
            acc1[0] = ffma2(P1, (u64)w0.x,  acc1[0]);
            acc1[1] = ffma2(P1, (u64)w0.y,  acc1[1]);
            acc1[2] = ffma2(P1, (u64)w1.x,  acc1[2]);
            acc1[3] = ffma2(P1, (u64)w1.y,  acc1[3]);
            acc1[4] = ffma2(P1, (u64)w2v.x, acc1[4]);
            acc1[5] = ffma2(P1, (u64)w2v.y, acc1[5]);
            acc1[6] = ffma2(P1, (u64)w3.x,  acc1[6]);
            acc1[7] = ffma2(P1, (u64)w3.y,  acc1[7]);
        }
        __syncthreads();
    }

    // ------------------- MID/GLO PHASE: 12 chunks of 64 tokens -------------
    auto stage = [&](int ci, int buf) {
        int tk = ci*64 + srow;
        const float* src;
        if (tk < 576)       src = g_KVmid + ((size_t)(b*576 + tk))*256;
        else if (tk < NTOK) src = g_KVglo + ((size_t)(b*144 + tk-576))*256;
        else                src = kvb;
        uint32_t dst = (uint32_t)__cvta_generic_to_shared(ds + buf*16384 + srow*256 + scol);
#pragma unroll
        for (int i = 0; i < 8; i++) cp16(dst + i*16, src + scol + i*4);
        asm volatile("cp.async.commit_group;");
    };

    stage(0, 0);
    for (int ci = 0; ci < NCH; ci++) {
        if (ci + 1 < NCH) {
            stage(ci+1, (ci+1)&1);
            asm volatile("cp.async.wait_group 1;");
        } else {
            asm volatile("cp.async.wait_group 0;");
        }
        __syncthreads();

        int len = (ci == NCH-1) ? 16 : 64;
        int n = len >> 1;                     // rows per half
        const float* kb = ds + (ci&1)*16384 + (th*n)*256 + h*16;
#pragma unroll 4
        for (int j = 0; j < n; j++) {
            const longlong2* kp = (const longlong2*)(kb + j*256);
            longlong2 a0 = kp[0], a1 = kp[1], a2 = kp[2], a3 = kp[3];

            u64 da = ffma2(q0[1], (u64)a0.y, fmul2(q0[0], (u64)a0.x));
            da = ffma2(q0[2], (u64)a1.x, da);
            da = ffma2(q0[3], (u64)a1.y, da);
            u64 db = ffma2(q0[5], (u64)a2.y, fmul2(q0[4], (u64)a2.x));
            db = ffma2(q0[6], (u64)a3.x, db);
            db = ffma2(q0[7], (u64)a3.y, db);
            u64 d0 = fadd2(da, db);

            u64 ea = ffma2(q1[1], (u64)a0.y, fmul2(q1[0], (u64)a0.x));
            ea = ffma2(q1[2], (u64)a1.x, ea);
            ea = ffma2(q1[3], (u64)a1.y, ea);
            u64 eb = ffma2(q1[5], (u64)a2.y, fmul2(q1[4], (u64)a2.x));
            eb = ffma2(q1[6], (u64)a3.x, eb);
            eb = ffma2(q1[7], (u64)a3.y, eb);
            u64 d1 = fadd2(ea, eb);

            float a, bb;
            up2(d0, a, bb); float p0 = ex2f(a + bb);
            up2(d1, a, bb); float p1 = ex2f(a + bb);
            ls0 += p0; ls1 += p1;
            u64 P0 = pk2(p0, p0), P1 = pk2(p1, p1);

            const longlong2* vp = (const longlong2*)(kb + j*256 + 128);
            longlong2 v0 = vp[0], v1 = vp[1], v2 = vp[2], v3 = vp[3];
            acc0[0] = ffma2(P0, (u64)v0.x, acc0[0]);
            acc0[1] = ffma2(P0, (u64)v0.y, acc0[1]);
            acc0[2] = ffma2(P0, (u64)v1.x, acc0[2]);
            acc0[3] = ffma2(P0, (u64)v1.y, acc0[3]);
            acc0[4] = ffma2(P0, (u64)v2.x, acc0[4]);
            acc0[5] = ffma2(P0, (u64)v2.y, acc0[5]);
            acc0[6] = ffma2(P0, (u64)v3.x, acc0[6]);
            acc0[7] = ffma2(P0, (u64)v3.y, acc0[7]);
            acc1[0] = ffma2(P1, (u64)v0.x, acc1[0]);
            acc1[1] = ffma2(P1, (u64)v0.y, acc1[1]);
            acc1[2] = ffma2(P1, (u64)v1.x, acc1[2]);
            acc1[3] = ffma2(P1, (u64)v1.y, acc1[3]);
            acc1[4] = ffma2(P1, (u64)v2.x, acc1[4]);
            acc1[5] = ffma2(P1, (u64)v2.y, acc1[5]);
            acc1[6] = ffma2(P1, (u64)v3.x, acc1[6]);
            acc1[7] = ffma2(P1, (u64)v3.y, acc1[7]);
        }
        __syncthreads();
    }

    // ------------------- merge halves, normalize, epilogue -----------------
    float* att = ds;                    // [64][132]
    float* lsm = ds + 64*132;           // [64][8]
    float* wsm = ds + 64*132 + 64*8;    // [16][132]

    if (th == 0) {
        float* r0 = &att[qg0*132 + h*16];
        float* r1 = &att[qg1*132 + h*16];
#pragma unroll
        for (int i = 0; i < 8; i++) {
            float a, bb;
            up2(acc0[i], a, bb); r0[2*i] = a; r0[2*i+1] = bb;
            up2(acc1[i], a, bb); r1[2*i] = a; r1[2*i+1] = bb;
        }
        lsm[qg0*8 + h] = ls0;
        lsm[qg1*8 + h] = ls1;
    }
    __syncthreads();
    if (th == 1) {
        float inv0 = 1.f / (lsm[qg0*8 + h] + ls0);
        float inv1 = 1.f / (lsm[qg1*8 + h] + ls1);
        float* r0 = &att[qg0*132 + h*16];
        float* r1 = &att[qg1*132 + h*16];
#pragma unroll
        for (int i = 0; i < 8; i++) {
            float a, bb;
            up2(acc0[i], a, bb);
            r0[2*i]   = (r0[2*i]   + a ) * inv0;
            r0[2*i+1] = (r0[2*i+1] + bb) * inv0;
            up2(acc1[i], a, bb);
            r1[2*i]   = (r1[2*i]   + a ) * inv1;
            r1[2*i+1] = (r1[2*i+1] + bb) * inv1;
        }
    }
    __syncthreads();

    // out projection: thread = (aqi = tid>>3, og = tid&7)
    int aqi = tid >> 3, og = tid & 7;
    float o[16];
#pragma unroll 1
    for (int ch = 0; ch < 8; ch++) {
        {
            int row = tid >> 5, quad = tid & 31;
            *(float4*)&wsm[row*132 + quad*4] =
                *(const float4*)(ow + (size_t)(ch*16 + row)*128 + quad*4);
        }
        __syncthreads();
        u64 r0p = 0ull, r1p = 0ull;
#pragma unroll
        for (int k4 = 0; k4 < 32; k4++) {
            longlong2 av = *(const longlong2*)&att[aqi*132 + k4*4];
            longlong2 w0 = *(const longlong2*)&wsm[og*132 + k4*4];
            longlong2 w1 = *(const longlong2*)&wsm[(og+8)*132 + k4*4];
            r0p = ffma2((u64)av.x, (u64)w0.x, r0p);
            r0p = ffma2((u64)av.y, (u64)w0.y, r0p);
            r1p = ffma2((u64)av.x, (u64)w1.x, r1p);
            r1p = ffma2((u64)av.y, (u64)w1.y, r1p);
        }
        float a, bb;
        up2(r0p, a, bb); o[ch*2]   = a + bb;
        up2(r1p, a, bb); o[ch*2+1] = a + bb;
        __syncthreads();
    }

    // residual add + NCHW scatter store
    {
        int qi = aqi & 15, wq = aqi >> 4;
        int wy = gy*2 + (wq>>1), wx = gx*2 + (wq&1);
        int py = wy*4 + (qi>>2), px = wx*4 + (qi&3);
#pragma unroll
        for (int ch = 0; ch < 8; ch++) {
#pragma unroll
            for (int u2 = 0; u2 < 2; u2++) {
                int oc = ch*16 + u2*8 + og;
                size_t gi = (((size_t)b*128 + oc)*48 + py)*48 + px;
                out[gi] = o[ch*2+u2] + ob[oc] + feat[gi];
            }
        }
    }
}

// ============================================================================
extern "C" void kernel_launch(void* const* d_in, const int* in_sizes, int n_in,
                              void* d_out, int out_size) {
    const float* feat = (const float*)d_in[0];
    const float* lnw  = (const float*)d_in[1];
    const float* lnb  = (const float*)d_in[2];
    const float* qw   = (const float*)d_in[3];
    const float* qb   = (const float*)d_in[4];
    const float* kvw  = (const float*)d_in[5];
    const float* kvb  = (const float*)d_in[6];
    const float* ow   = (const float*)d_in[7];
    const float* ob   = (const float*)d_in[8];
    float* out = (float*)d_out;

    cudaFuncSetAttribute(k3_attn, cudaFuncAttributeMaxDynamicSharedMemorySize, 131072);

    k01_proj<<<dim3(144, 3), 256>>>(feat, lnw, lnb, qw, qb, kvw, kvb);
    k2_pool<<<2880, 256>>>();
    k3_attn<<<144, 512, 131072>>>(feat, kvb, ow, ob, out);
}